// round 14
// baseline (speedup 1.0000x reference)
#include <cuda_runtime.h>
#include <cuda_bf16.h>
#include <cstdint>

#define NS    8192
#define NHALF 4096
#define D     256
#define TS    128          // output tile (M=N)
#define KC    128          // int8 K elems per smem stage (128 B rows)
#define NSTAGE (D / KC)    // 2
#define NTILE  64          // NS / TS
#define NBLK   (NTILE * (NTILE + 1) / 2)   // 2080 upper-triangle tiles
#define PREPB  256         // prep chunks (32 rows each), done by CTAs bid<256

// ---- device-global scratch (no allocs allowed) ------------------------------
__device__ double g_acc;
__device__ float  g_colpart[PREPB * D];      // per-chunk column-sum partials
__device__ float  g_sqpart[PREPB];           // per-chunk sum-of-norms partials
__device__ float  g_sq[NS];                  // exact fp32 row norms
__device__ float  g_sc[NS];                  // per-row quant scale s_i = max/127
__device__ float  g_C;                       // log2(e) / (16*b)
__device__ unsigned g_pctr = 0;              // prep completion counter
__device__ unsigned g_mctr = 0;              // tile completion counter
__device__ unsigned g_ready = 0;             // prep-done flag (release/acquire)
__device__ __align__(16) int8_t g_Y[(size_t)NS * D];   // 2 MB quantized rows

// ---- helpers ----------------------------------------------------------------
__device__ __forceinline__ float ex2f_fast(float x) {
    float y; asm("ex2.approx.f32 %0, %1;" : "=f"(y) : "f"(x)); return y;
}
__device__ __forceinline__ uint32_t smem_u32(const void* p) {
    uint32_t a;
    asm("{ .reg .u64 t; cvta.to.shared.u64 t, %1; cvt.u32.u64 %0, t; }" : "=r"(a) : "l"(p));
    return a;
}
__device__ __forceinline__ void cp16(uint32_t dst, const void* src) {
    asm volatile("cp.async.cg.shared.global [%0], [%1], 16;" :: "r"(dst), "l"(src));
}
#define CP_COMMIT() asm volatile("cp.async.commit_group;" ::: "memory")
#define CP_WAIT(n)  asm volatile("cp.async.wait_group %0;" :: "n"(n) : "memory")

__device__ __forceinline__ void ldm4(uint32_t* r, uint32_t a) {
    asm volatile("ldmatrix.sync.aligned.m8n8.x4.shared.b16 {%0,%1,%2,%3}, [%4];"
        : "=r"(r[0]), "=r"(r[1]), "=r"(r[2]), "=r"(r[3]) : "r"(a));
}
// s8 IMMA m16n8k32, s32 accumulate
__device__ __forceinline__ void imma16832(int* c, const uint32_t* a, const uint32_t* b) {
    asm volatile("mma.sync.aligned.m16n8k32.row.col.s32.s8.s8.s32 "
        "{%0,%1,%2,%3}, {%4,%5,%6,%7}, {%8,%9}, {%0,%1,%2,%3};"
        : "+r"(c[0]), "+r"(c[1]), "+r"(c[2]), "+r"(c[3])
        : "r"(a[0]), "r"(a[1]), "r"(a[2]), "r"(a[3]), "r"(b[0]), "r"(b[1]));
}

// ---- packed f32x2 (Blackwell FFMA2/FADD2 pipe) ------------------------------
__device__ __forceinline__ uint64_t pk2(float lo, float hi) {
    uint64_t r; asm("mov.b64 %0, {%1, %2};" : "=l"(r) : "f"(lo), "f"(hi)); return r;
}
__device__ __forceinline__ void unpk2(float& lo, float& hi, uint64_t v) {
    asm("mov.b64 {%0, %1}, %2;" : "=f"(lo), "=f"(hi) : "l"(v));
}
__device__ __forceinline__ uint64_t mul2(uint64_t a, uint64_t b) {
    uint64_t r; asm("mul.rn.f32x2 %0, %1, %2;" : "=l"(r) : "l"(a), "l"(b)); return r;
}
__device__ __forceinline__ uint64_t add2(uint64_t a, uint64_t b) {
    uint64_t r; asm("add.rn.f32x2 %0, %1, %2;" : "=l"(r) : "l"(a), "l"(b)); return r;
}
__device__ __forceinline__ uint64_t fma2(uint64_t a, uint64_t b, uint64_t c) {
    uint64_t r; asm("fma.rn.f32x2 %0, %1, %2, %3;" : "=l"(r) : "l"(a), "l"(b), "l"(c)); return r;
}

__device__ __forceinline__ unsigned ld_acq(unsigned* p) {
    unsigned v; asm volatile("ld.acquire.gpu.u32 %0, [%1];" : "=r"(v) : "l"(p)); return v;
}

// SW128-style XOR swizzle for tiles with 128-byte rows (cp path only).
__device__ __forceinline__ uint32_t swz(uint32_t off) {
    return off ^ ((off >> 3) & 0x70);
}

__device__ __forceinline__ const float* row_ptr(const float* __restrict__ s,
                                                const float* __restrict__ t, int i) {
    return (i < NHALF) ? (s + (size_t)i * D) : (t + (size_t)(i - NHALF) * D);
}

// ---------------------------------------------------------------------------
// Fused single kernel: prep (CTAs 0..255) -> acquire gate -> IMMA Gram tile +
// Gaussian epilogue (all 2080 CTAs) -> last CTA writes output.
#define STAGE_BYTES 32768                    // A(16KB) + B(16KB)
#define SMEM_TOTAL  (2 * STAGE_BYTES)        // 64KB dyn; 3 CTAs/SM

__device__ __forceinline__ void load_frags(uint32_t Ab, uint32_t Bb, uint32_t koff,
                                           const uint32_t* ra, const uint32_t* rb,
                                           uint32_t afr[4][4], uint32_t bfr[8][2]) {
    #pragma unroll
    for (int i = 0; i < 4; ++i)
        ldm4(afr[i], Ab + ra[i] + koff);
    #pragma unroll
    for (int j2 = 0; j2 < 4; ++j2) {
        uint32_t q[4];
        ldm4(q, Bb + rb[j2] + koff);
        bfr[j2 * 2 + 0][0] = q[0]; bfr[j2 * 2 + 0][1] = q[2];
        bfr[j2 * 2 + 1][0] = q[1]; bfr[j2 * 2 + 1][1] = q[3];
    }
}

__global__ __launch_bounds__(128, 3) void k_all(float* __restrict__ out,
                                                const float* __restrict__ s,
                                                const float* __restrict__ t) {
    extern __shared__ char sm[];
    __shared__ __align__(16) float s_nCi[128], s_nCj[128], s_sci[128], s_scj[128];
    __shared__ float s_red[128];
    __shared__ float wsum[4];
    __shared__ unsigned s_done;
    uint32_t sbase = smem_u32(sm);

    int tid  = threadIdx.x;
    int warp = tid >> 5, lane = tid & 31;
    int bid  = blockIdx.x;

    // ---------------- prep phase (CTAs 0..PREPB-1) ----------------
    if (bid < PREPB) {
        float* colp = (float*)sm;            // 4 warps x 256 cols (reuses stage smem)
        float4 ca = make_float4(0.f, 0.f, 0.f, 0.f);
        float4 cb = make_float4(0.f, 0.f, 0.f, 0.f);
        float normsum = 0.0f;

        #pragma unroll 2
        for (int r = 0; r < 8; ++r) {
            int row = bid * 32 + warp * 8 + r;
            const float4* p = (const float4*)row_ptr(s, t, row);
            float4 a = p[lane];          // cols 4*lane .. 4*lane+3
            float4 b = p[lane + 32];     // cols 128+4*lane ..

            float v = a.x * a.x + a.y * a.y + a.z * a.z + a.w * a.w
                    + b.x * b.x + b.y * b.y + b.z * b.z + b.w * b.w;
            float m = fmaxf(fmaxf(fmaxf(fabsf(a.x), fabsf(a.y)), fmaxf(fabsf(a.z), fabsf(a.w))),
                            fmaxf(fmaxf(fabsf(b.x), fabsf(b.y)), fmaxf(fabsf(b.z), fabsf(b.w))));
            #pragma unroll
            for (int o = 16; o; o >>= 1) {
                v += __shfl_xor_sync(0xffffffffu, v, o);
                m  = fmaxf(m, __shfl_xor_sync(0xffffffffu, m, o));
            }
            if (lane == 0) {
                g_sq[row] = v;
                g_sc[row] = m * (1.0f / 127.0f);
                normsum += v;
            }

            float inv = (m > 0.0f) ? (127.0f / m) : 0.0f;
            int qa0 = __float2int_rn(a.x * inv), qa1 = __float2int_rn(a.y * inv);
            int qa2 = __float2int_rn(a.z * inv), qa3 = __float2int_rn(a.w * inv);
            int qb0 = __float2int_rn(b.x * inv), qb1 = __float2int_rn(b.y * inv);
            int qb2 = __float2int_rn(b.z * inv), qb3 = __float2int_rn(b.w * inv);
            uint32_t ua = (uint32_t)(qa0 & 0xFF) | ((uint32_t)(qa1 & 0xFF) << 8)
                        | ((uint32_t)(qa2 & 0xFF) << 16) | ((uint32_t)qa3 << 24);
            uint32_t ub = (uint32_t)(qb0 & 0xFF) | ((uint32_t)(qb1 & 0xFF) << 8)
                        | ((uint32_t)(qb2 & 0xFF) << 16) | ((uint32_t)qb3 << 24);
            uint32_t* yrow = (uint32_t*)(g_Y + (size_t)row * D);
            yrow[lane]      = ua;
            yrow[lane + 32] = ub;

            ca.x += a.x; ca.y += a.y; ca.z += a.z; ca.w += a.w;
            cb.x += b.x; cb.y += b.y; cb.z += b.z; cb.w += b.w;
        }

        ((float4*)(colp + warp * 256))[lane]      = ca;
        ((float4*)(colp + warp * 256))[lane + 32] = cb;
        if (lane == 0) wsum[warp] = normsum;
        __syncthreads();

        // 128 threads, 2 columns each
        float cs0 = 0.0f, cs1 = 0.0f;
        #pragma unroll
        for (int w = 0; w < 4; ++w) {
            cs0 += colp[w * 256 + tid];
            cs1 += colp[w * 256 + tid + 128];
        }
        g_colpart[bid * D + tid]       = cs0;
        g_colpart[bid * D + tid + 128] = cs1;
        if (tid == 0) {
            g_sqpart[bid] = wsum[0] + wsum[1] + wsum[2] + wsum[3];
            g_acc = 0.0;
        }

        __threadfence();
        if (tid == 0) s_done = atomicAdd(&g_pctr, 1u);
        __syncthreads();

        if (s_done == PREPB - 1) {
            // tail: bandwidth constant (all 128 threads)
            float c0 = 0.0f, c1 = 0.0f;
            #pragma unroll 4
            for (int b = 0; b < PREPB; ++b) {
                c0 += g_colpart[b * D + tid];
                c1 += g_colpart[b * D + tid + 128];
            }
            s_red[tid] = c0 * c0 + c1 * c1;
            __syncthreads();
            for (int o = 64; o; o >>= 1) { if (tid < o) s_red[tid] += s_red[tid + o]; __syncthreads(); }
            float csq = s_red[0];
            __syncthreads();
            s_red[tid] = g_sqpart[tid] + g_sqpart[tid + 128];
            __syncthreads();
            for (int o = 64; o; o >>= 1) { if (tid < o) s_red[tid] += s_red[tid + o]; __syncthreads(); }
            if (tid == 0) {
                double suml2 = 2.0 * (double)NS * (double)s_red[0] - 2.0 * (double)csq;
                double bw = suml2 / ((double)NS * (double)NS - (double)NS);
                double b = bw / 4.0;   // KERNEL_MUL^(KERNEL_NUM//2) = 2^2
                g_C = (float)(1.4426950408889634 / (16.0 * b));
                g_pctr = 0;            // reset for next graph replay
                __threadfence();
                atomicExch(&g_ready, 1u);   // release
            }
        }
    }

    // ---------------- acquire gate ----------------
    if (ld_acq(&g_ready) == 0) {
        do { __nanosleep(128); } while (ld_acq(&g_ready) == 0);
    }
    __syncthreads();    // all threads past gate; prep smem reuse now safe

    // ---------------- tile phase ----------------
    // linear bid -> (ib, jb), jb >= ib.
    int ib = (int)(64.5f - sqrtf(64.5f * 64.5f - 2.0f * (float)bid));
    #pragma unroll 1
    while ((64 * (ib + 1) - ((ib + 1) * ib) / 2) <= bid) ++ib;
    #pragma unroll 1
    while ((64 * ib - (ib * (ib - 1)) / 2) > bid) --ib;
    int jb = ib + (bid - (64 * ib - (ib * (ib - 1)) / 2));

    int wm = warp >> 1, wn = warp & 1;        // warp tile: rows wm*64, cols wn*64
    int rI = ib * TS, rJ = jb * TS;

    float C = g_C;
    float twoC = 2.0f * C;
    s_nCi[tid] = -C * g_sq[rI + tid];
    s_nCj[tid] = -C * g_sq[rJ + tid];
    s_sci[tid] = twoC * g_sc[rI + tid];       // pre-scaled row quant scale
    s_scj[tid] = g_sc[rJ + tid];

    const int8_t* YA = g_Y + (size_t)rI * D;
    const int8_t* YB = g_Y + (size_t)rJ * D;

    // hoisted LDSM addressing: swz(row*128+kb) == row*128 + (kb ^ ((lane&7)<<4))
    int lane15 = lane & 15;
    uint32_t xr  = (uint32_t)((lane & 7) << 4);
    uint32_t kb0 = (uint32_t)((lane >> 4) * 16);
    uint32_t ra[4], rb[4];
    #pragma unroll
    for (int i = 0; i < 4; ++i) {
        ra[i] = (uint32_t)((wm * 64 + i * 16 + lane15) * 128);
        rb[i] = (uint32_t)((wn * 64 + i * 16 + lane15) * 128);
    }

    auto issue_stage = [&](int st, int buf) {
        int k0 = st * KC;
        uint32_t base = sbase + buf * STAGE_BYTES;
        #pragma unroll
        for (int tt = 0; tt < 8; ++tt) {
            int chunk = tid + tt * 128;          // 0..1023
            int r = chunk >> 3, c16 = chunk & 7;
            uint32_t d = swz((uint32_t)(r * 128 + c16 * 16));
            cp16(base + d,         YA + (size_t)r * D + k0 + c16 * 16);
            cp16(base + 16384 + d, YB + (size_t)r * D + k0 + c16 * 16);
        }
        CP_COMMIT();
    };

    int acc[4][8][4] = {};
    uint32_t afr[2][4][4], bfr[2][8][2];

    issue_stage(0, 0);
    issue_stage(1, 1);

    __syncthreads();    // s_nCi..s_scj visible to all warps before epilogue

    #pragma unroll
    for (int st = 0; st < NSTAGE; ++st) {
        if (st == 0) CP_WAIT(1);
        else         CP_WAIT(0);
        __syncthreads();

        uint32_t Ab = sbase + st * STAGE_BYTES;
        uint32_t Bb = Ab + 16384;

        load_frags(Ab, Bb, kb0 ^ xr, ra, rb, afr[0], bfr[0]);
        #pragma unroll
        for (int kk = 0; kk < 4; ++kk) {       // 4 k-steps of k=32 per stage
            int cur = kk & 1;
            if (kk < 3) {
                uint32_t koff = ((uint32_t)((kk + 1) << 5) | kb0) ^ xr;
                load_frags(Ab, Bb, koff, ra, rb, afr[cur ^ 1], bfr[cur ^ 1]);
            }
            #pragma unroll
            for (int i = 0; i < 4; ++i)
                #pragma unroll
                for (int j = 0; j < 8; ++j)
                    imma16832(acc[i][j], afr[cur][i], bfr[cur][j]);
        }
        __syncthreads();
    }

    // ---- fused epilogue (packed f32x2 throughout):
    //   arg2 = fma2(mul2(si2, sj2), accf2, add2(ni2, nj2));  u = exp2(arg)
    //   powersum = u + u^2 + u^4 + u^8 + u^16  (packed pairs)
    uint64_t part2 = pk2(0.0f, 0.0f);
    #pragma unroll
    for (int i = 0; i < 4; ++i) {
        int r_lo = wm * 64 + i * 16 + (lane >> 2);
        uint64_t ni2_lo = pk2(s_nCi[r_lo],     s_nCi[r_lo]);
        uint64_t ni2_hi = pk2(s_nCi[r_lo + 8], s_nCi[r_lo + 8]);
        uint64_t si2_lo = pk2(s_sci[r_lo],     s_sci[r_lo]);
        uint64_t si2_hi = pk2(s_sci[r_lo + 8], s_sci[r_lo + 8]);
        #pragma unroll
        for (int j = 0; j < 8; ++j) {
            int c_lo = wn * 64 + j * 8 + (lane & 3) * 2;
            uint64_t nj2 = *reinterpret_cast<const uint64_t*>(&s_nCj[c_lo]);
            uint64_t sj2 = *reinterpret_cast<const uint64_t*>(&s_scj[c_lo]);
            uint64_t arg_lo = fma2(mul2(si2_lo, sj2),
                                   pk2((float)acc[i][j][0], (float)acc[i][j][1]),
                                   add2(ni2_lo, nj2));
            uint64_t arg_hi = fma2(mul2(si2_hi, sj2),
                                   pk2((float)acc[i][j][2], (float)acc[i][j][3]),
                                   add2(ni2_hi, nj2));
            float x0, x1, x2, x3;
            unpk2(x0, x1, arg_lo);
            unpk2(x2, x3, arg_hi);
            uint64_t u_ab = pk2(ex2f_fast(x0), ex2f_fast(x1));
            uint64_t u_cd = pk2(ex2f_fast(x2), ex2f_fast(x3));
            #pragma unroll
            for (int e = 0; e < 2; ++e) {
                uint64_t u = (e == 0) ? u_ab : u_cd;
                uint64_t u2 = mul2(u, u);
                uint64_t u4 = mul2(u2, u2);
                uint64_t u8 = mul2(u4, u4);
                uint64_t hi = fma2(u8, u8, u8);           // u16 + u8
                part2 = add2(part2, add2(add2(u, u2), add2(u4, hi)));
            }
        }
    }
    float plo, phi;
    unpk2(plo, phi, part2);
    float partial = plo + phi;
    float sgn = ((ib < 32) == (jb < 32)) ? 1.0f : -1.0f;
    partial *= (ib == jb) ? sgn : 2.0f * sgn;

    s_red[tid] = partial;
    __syncthreads();
    if (tid < 64) s_red[tid] += s_red[tid + 64];
    __syncthreads();
    if (tid < 32) {
        float v = s_red[tid] + s_red[tid + 32];
        #pragma unroll
        for (int o = 16; o; o >>= 1) v += __shfl_down_sync(0xffffffffu, v, o);
        if (tid == 0) atomicAdd(&g_acc, (double)v);
    }

    // last CTA writes the result; resets flags for next graph replay
    if (tid == 0) {
        __threadfence();
        unsigned d = atomicAdd(&g_mctr, 1u);
        if (d == NBLK - 1) {
            out[0] = (float)(g_acc / ((double)NHALF * (double)NHALF));
            g_mctr  = 0;
            g_ready = 0;
        }
    }
}

// ---------------------------------------------------------------------------
extern "C" void kernel_launch(void* const* d_in, const int* in_sizes, int n_in,
                              void* d_out, int out_size) {
    const float* s = (const float*)d_in[0];
    const float* t = (const float*)d_in[1];
    float* out = (float*)d_out;

    cudaFuncSetAttribute(k_all, cudaFuncAttributeMaxDynamicSharedMemorySize, SMEM_TOTAL);

    k_all<<<NBLK, 128, SMEM_TOTAL>>>(out, s, t);
}

// round 15
// speedup vs baseline: 1.1540x; 1.1540x over previous
#include <cuda_runtime.h>
#include <cuda_bf16.h>
#include <cstdint>

#define NS    8192
#define NHALF 4096
#define D     256
#define TS    128          // output tile (M=N)
#define KC    128          // int8 K elems per smem stage (128 B rows)
#define NSTAGE (D / KC)    // 2
#define NTILE  64          // NS / TS
#define NBLK   (NTILE * (NTILE + 1) / 2)   // 2080 upper-triangle tiles
#define PREPB  256         // k_prep blocks (32 rows each)

// ---- device-global scratch (no allocs allowed) ------------------------------
__device__ double g_acc;
__device__ float  g_colpart[PREPB * D];      // per-block column-sum partials
__device__ float  g_sqpart[PREPB];           // per-block sum-of-norms partials
__device__ float  g_sq[NS];                  // exact fp32 row norms
__device__ float  g_sc[NS];                  // per-row quant scale s_i = max/127
__device__ float  g_C;                       // log2(e) / (16*b)
__device__ unsigned g_pctr = 0;              // k_prep completion counter
__device__ unsigned g_mctr = 0;              // k_mmd completion counter
__device__ __align__(16) int8_t g_Y[(size_t)NS * D];   // 2 MB quantized rows

// ---- helpers ----------------------------------------------------------------
__device__ __forceinline__ float ex2f_fast(float x) {
    float y; asm("ex2.approx.f32 %0, %1;" : "=f"(y) : "f"(x)); return y;
}
__device__ __forceinline__ uint32_t smem_u32(const void* p) {
    uint32_t a;
    asm("{ .reg .u64 t; cvta.to.shared.u64 t, %1; cvt.u32.u64 %0, t; }" : "=r"(a) : "l"(p));
    return a;
}
__device__ __forceinline__ void cp16(uint32_t dst, const void* src) {
    asm volatile("cp.async.cg.shared.global [%0], [%1], 16;" :: "r"(dst), "l"(src));
}
#define CP_COMMIT() asm volatile("cp.async.commit_group;" ::: "memory")
#define CP_WAIT(n)  asm volatile("cp.async.wait_group %0;" :: "n"(n) : "memory")

__device__ __forceinline__ void ldm4(uint32_t* r, uint32_t a) {
    asm volatile("ldmatrix.sync.aligned.m8n8.x4.shared.b16 {%0,%1,%2,%3}, [%4];"
        : "=r"(r[0]), "=r"(r[1]), "=r"(r[2]), "=r"(r[3]) : "r"(a));
}
// s8 IMMA m16n8k32, s32 accumulate
__device__ __forceinline__ void imma16832(int* c, const uint32_t* a, const uint32_t* b) {
    asm volatile("mma.sync.aligned.m16n8k32.row.col.s32.s8.s8.s32 "
        "{%0,%1,%2,%3}, {%4,%5,%6,%7}, {%8,%9}, {%0,%1,%2,%3};"
        : "+r"(c[0]), "+r"(c[1]), "+r"(c[2]), "+r"(c[3])
        : "r"(a[0]), "r"(a[1]), "r"(a[2]), "r"(a[3]), "r"(b[0]), "r"(b[1]));
}

// ---- packed f32x2 (Blackwell FFMA2/FADD2 pipe) ------------------------------
__device__ __forceinline__ uint64_t pk2(float lo, float hi) {
    uint64_t r; asm("mov.b64 %0, {%1, %2};" : "=l"(r) : "f"(lo), "f"(hi)); return r;
}
__device__ __forceinline__ void unpk2(float& lo, float& hi, uint64_t v) {
    asm("mov.b64 {%0, %1}, %2;" : "=f"(lo), "=f"(hi) : "l"(v));
}
__device__ __forceinline__ uint64_t mul2(uint64_t a, uint64_t b) {
    uint64_t r; asm("mul.rn.f32x2 %0, %1, %2;" : "=l"(r) : "l"(a), "l"(b)); return r;
}
__device__ __forceinline__ uint64_t add2(uint64_t a, uint64_t b) {
    uint64_t r; asm("add.rn.f32x2 %0, %1, %2;" : "=l"(r) : "l"(a), "l"(b)); return r;
}
__device__ __forceinline__ uint64_t fma2(uint64_t a, uint64_t b, uint64_t c) {
    uint64_t r; asm("fma.rn.f32x2 %0, %1, %2, %3;" : "=l"(r) : "l"(a), "l"(b), "l"(c)); return r;
}

// SW128-style XOR swizzle for tiles with 128-byte rows (cp path only).
__device__ __forceinline__ uint32_t swz(uint32_t off) {
    return off ^ ((off >> 3) & 0x70);
}

__device__ __forceinline__ const float* row_ptr(const float* __restrict__ s,
                                                const float* __restrict__ t, int i) {
    return (i < NHALF) ? (s + (size_t)i * D) : (t + (size_t)(i - NHALF) * D);
}

// ---------------------------------------------------------------------------
// Fused prep: per-row L2 norm (exact fp32), per-row int8 quantization,
// per-block column-sum/norm-sum partials; last block computes bandwidth g_C.
__global__ __launch_bounds__(256) void k_prep(const float* __restrict__ s,
                                              const float* __restrict__ t) {
    __shared__ float colp[8][256];
    __shared__ float wsum[8];
    __shared__ unsigned s_done;
    int warp = threadIdx.x >> 5, lane = threadIdx.x & 31;

    float4 ca = make_float4(0.f, 0.f, 0.f, 0.f);
    float4 cb = make_float4(0.f, 0.f, 0.f, 0.f);
    float normsum = 0.0f;

    #pragma unroll
    for (int r = 0; r < 4; ++r) {
        int row = blockIdx.x * 32 + warp * 4 + r;
        const float4* p = (const float4*)row_ptr(s, t, row);
        float4 a = p[lane];          // cols 4*lane .. 4*lane+3
        float4 b = p[lane + 32];     // cols 128+4*lane ..

        float v = a.x * a.x + a.y * a.y + a.z * a.z + a.w * a.w
                + b.x * b.x + b.y * b.y + b.z * b.z + b.w * b.w;
        float m = fmaxf(fmaxf(fmaxf(fabsf(a.x), fabsf(a.y)), fmaxf(fabsf(a.z), fabsf(a.w))),
                        fmaxf(fmaxf(fabsf(b.x), fabsf(b.y)), fmaxf(fabsf(b.z), fabsf(b.w))));
        #pragma unroll
        for (int o = 16; o; o >>= 1) {
            v += __shfl_xor_sync(0xffffffffu, v, o);
            m  = fmaxf(m, __shfl_xor_sync(0xffffffffu, m, o));
        }
        if (lane == 0) {
            g_sq[row] = v;
            g_sc[row] = m * (1.0f / 127.0f);
            normsum += v;
        }

        // quantize: q = round(x * 127/m), pack 4 x s8 per u32
        float inv = (m > 0.0f) ? (127.0f / m) : 0.0f;
        int qa0 = __float2int_rn(a.x * inv), qa1 = __float2int_rn(a.y * inv);
        int qa2 = __float2int_rn(a.z * inv), qa3 = __float2int_rn(a.w * inv);
        int qb0 = __float2int_rn(b.x * inv), qb1 = __float2int_rn(b.y * inv);
        int qb2 = __float2int_rn(b.z * inv), qb3 = __float2int_rn(b.w * inv);
        uint32_t ua = (uint32_t)(qa0 & 0xFF) | ((uint32_t)(qa1 & 0xFF) << 8)
                    | ((uint32_t)(qa2 & 0xFF) << 16) | ((uint32_t)qa3 << 24);
        uint32_t ub = (uint32_t)(qb0 & 0xFF) | ((uint32_t)(qb1 & 0xFF) << 8)
                    | ((uint32_t)(qb2 & 0xFF) << 16) | ((uint32_t)qb3 << 24);
        uint32_t* yrow = (uint32_t*)(g_Y + (size_t)row * D);
        yrow[lane]      = ua;
        yrow[lane + 32] = ub;

        ca.x += a.x; ca.y += a.y; ca.z += a.z; ca.w += a.w;
        cb.x += b.x; cb.y += b.y; cb.z += b.z; cb.w += b.w;
    }

    ((float4*)colp[warp])[lane]      = ca;
    ((float4*)colp[warp])[lane + 32] = cb;
    if (lane == 0) wsum[warp] = normsum;
    __syncthreads();

    int tid = threadIdx.x;           // 0..255 = column index
    float cs = 0.0f;
    #pragma unroll
    for (int w = 0; w < 8; ++w) cs += colp[w][tid];
    g_colpart[blockIdx.x * D + tid] = cs;
    if (tid == 0) {
        float ss = 0.0f;
        #pragma unroll
        for (int w = 0; w < 8; ++w) ss += wsum[w];
        g_sqpart[blockIdx.x] = ss;
        g_acc = 0.0;
    }

    // last-block bandwidth computation
    __threadfence();
    if (tid == 0) s_done = atomicAdd(&g_pctr, 1u);
    __syncthreads();
    if (s_done == PREPB - 1) {
        __shared__ float red[256];
        float c2 = 0.0f;
        #pragma unroll 8
        for (int b = 0; b < PREPB; ++b) c2 += g_colpart[b * D + tid];
        red[tid] = c2 * c2;
        __syncthreads();
        for (int o = 128; o; o >>= 1) { if (tid < o) red[tid] += red[tid + o]; __syncthreads(); }
        float csq = red[0];
        __syncthreads();
        red[tid] = g_sqpart[tid];        // PREPB == 256
        __syncthreads();
        for (int o = 128; o; o >>= 1) { if (tid < o) red[tid] += red[tid + o]; __syncthreads(); }
        if (tid == 0) {
            double suml2 = 2.0 * (double)NS * (double)red[0] - 2.0 * (double)csq;
            double bw = suml2 / ((double)NS * (double)NS - (double)NS);
            double b = bw / 4.0;     // KERNEL_MUL^(KERNEL_NUM//2) = 2^2
            g_C = (float)(1.4426950408889634 / (16.0 * b));
            g_pctr = 0;              // reset for next graph replay
        }
    }
}

// ---------------------------------------------------------------------------
// INT8 warp-IMMA fused Gram + Gaussian epilogue. 2080 CTAs, 4 warps each,
// 64x64 warp tiles over 128x128. K=256 int8 in 2 stages of 128 (128B rows),
// cp.async double-buffered, register double-buffered fragments, s8 IMMA k32.
// 3 CTAs/SM; fully-packed f32x2 epilogue.
#define STAGE_BYTES 32768                    // A(16KB) + B(16KB)
#define SMEM_TOTAL  (2 * STAGE_BYTES)        // 64KB dyn; 3 CTAs/SM ~ 200KB

__device__ __forceinline__ void load_frags(uint32_t Ab, uint32_t Bb, uint32_t koff,
                                           const uint32_t* ra, const uint32_t* rb,
                                           uint32_t afr[4][4], uint32_t bfr[8][2]) {
    #pragma unroll
    for (int i = 0; i < 4; ++i)
        ldm4(afr[i], Ab + ra[i] + koff);
    #pragma unroll
    for (int j2 = 0; j2 < 4; ++j2) {
        uint32_t q[4];
        ldm4(q, Bb + rb[j2] + koff);
        bfr[j2 * 2 + 0][0] = q[0]; bfr[j2 * 2 + 0][1] = q[2];
        bfr[j2 * 2 + 1][0] = q[1]; bfr[j2 * 2 + 1][1] = q[3];
    }
}

__global__ __launch_bounds__(128, 3) void k_mmd(float* __restrict__ out) {
    // linear bid -> (ib, jb), jb >= ib.
    int bid = blockIdx.x;
    int ib = (int)(64.5f - sqrtf(64.5f * 64.5f - 2.0f * (float)bid));
    #pragma unroll 1
    while ((64 * (ib + 1) - ((ib + 1) * ib) / 2) <= bid) ++ib;
    #pragma unroll 1
    while ((64 * ib - (ib * (ib - 1)) / 2) > bid) --ib;
    int jb = ib + (bid - (64 * ib - (ib * (ib - 1)) / 2));

    extern __shared__ char sm[];
    __shared__ __align__(16) float s_nCi[128], s_nCj[128], s_sci[128], s_scj[128];
    __shared__ float s_red[128];
    uint32_t sbase = smem_u32(sm);

    int tid  = threadIdx.x;
    int warp = tid >> 5, lane = tid & 31;
    int wm = warp >> 1, wn = warp & 1;        // warp tile: rows wm*64, cols wn*64
    int rI = ib * TS, rJ = jb * TS;

    float C = g_C;
    s_nCi[tid] = -C * g_sq[rI + tid];
    s_nCj[tid] = -C * g_sq[rJ + tid];
    s_sci[tid] = 2.0f * C * g_sc[rI + tid];   // pre-scaled row quant scale
    s_scj[tid] = g_sc[rJ + tid];

    const int8_t* YA = g_Y + (size_t)rI * D;
    const int8_t* YB = g_Y + (size_t)rJ * D;

    // hoisted LDSM addressing: swz(row*128+kb) == row*128 + (kb ^ ((lane&7)<<4))
    int lane15 = lane & 15;
    uint32_t xr  = (uint32_t)((lane & 7) << 4);
    uint32_t kb0 = (uint32_t)((lane >> 4) * 16);
    uint32_t ra[4], rb[4];
    #pragma unroll
    for (int i = 0; i < 4; ++i) {
        ra[i] = (uint32_t)((wm * 64 + i * 16 + lane15) * 128);
        rb[i] = (uint32_t)((wn * 64 + i * 16 + lane15) * 128);
    }

    auto issue_stage = [&](int st, int buf) {
        int k0 = st * KC;                      // byte offset within 256B row
        uint32_t base = sbase + buf * STAGE_BYTES;
        #pragma unroll
        for (int t = 0; t < 8; ++t) {
            int chunk = tid + t * 128;           // 0..1023
            int r = chunk >> 3, c16 = chunk & 7;
            uint32_t d = swz((uint32_t)(r * 128 + c16 * 16));
            cp16(base + d,         YA + (size_t)r * D + k0 + c16 * 16);
            cp16(base + 16384 + d, YB + (size_t)r * D + k0 + c16 * 16);
        }
        CP_COMMIT();
    };

    int acc[4][8][4] = {};
    uint32_t afr[2][4][4], bfr[2][8][2];

    issue_stage(0, 0);
    issue_stage(1, 1);

    #pragma unroll
    for (int st = 0; st < NSTAGE; ++st) {
        if (st == 0) CP_WAIT(1);
        else         CP_WAIT(0);
        __syncthreads();

        uint32_t Ab = sbase + st * STAGE_BYTES;
        uint32_t Bb = Ab + 16384;

        load_frags(Ab, Bb, kb0 ^ xr, ra, rb, afr[0], bfr[0]);
        #pragma unroll
        for (int kk = 0; kk < 4; ++kk) {       // 4 k-steps of k=32 per stage
            int cur = kk & 1;
            if (kk < 3) {
                uint32_t koff = ((uint32_t)((kk + 1) << 5) | kb0) ^ xr;
                load_frags(Ab, Bb, koff, ra, rb, afr[cur ^ 1], bfr[cur ^ 1]);
            }
            #pragma unroll
            for (int i = 0; i < 4; ++i)
                #pragma unroll
                for (int j = 0; j < 8; ++j)
                    imma16832(acc[i][j], afr[cur][i], bfr[cur][j]);
        }
        __syncthreads();
    }

    // ---- fused epilogue (fully packed f32x2):
    //   arg2 = fma2(mul2(si2, sj2), accf2, add2(ni2, nj2));  u = exp2(arg)
    //   powersum = u + u^2 + u^4 + u^8 + u^16  (packed pairs)
    uint64_t part2 = pk2(0.0f, 0.0f);
    #pragma unroll
    for (int i = 0; i < 4; ++i) {
        int r_lo = wm * 64 + i * 16 + (lane >> 2);
        uint64_t ni2_lo = pk2(s_nCi[r_lo],     s_nCi[r_lo]);
        uint64_t ni2_hi = pk2(s_nCi[r_lo + 8], s_nCi[r_lo + 8]);
        uint64_t si2_lo = pk2(s_sci[r_lo],     s_sci[r_lo]);
        uint64_t si2_hi = pk2(s_sci[r_lo + 8], s_sci[r_lo + 8]);
        #pragma unroll
        for (int j = 0; j < 8; ++j) {
            int c_lo = wn * 64 + j * 8 + (lane & 3) * 2;
            uint64_t nj2 = *reinterpret_cast<const uint64_t*>(&s_nCj[c_lo]);
            uint64_t sj2 = *reinterpret_cast<const uint64_t*>(&s_scj[c_lo]);
            uint64_t arg_lo = fma2(mul2(si2_lo, sj2),
                                   pk2((float)acc[i][j][0], (float)acc[i][j][1]),
                                   add2(ni2_lo, nj2));
            uint64_t arg_hi = fma2(mul2(si2_hi, sj2),
                                   pk2((float)acc[i][j][2], (float)acc[i][j][3]),
                                   add2(ni2_hi, nj2));
            float x0, x1, x2, x3;
            unpk2(x0, x1, arg_lo);
            unpk2(x2, x3, arg_hi);
            uint64_t u_ab = pk2(ex2f_fast(x0), ex2f_fast(x1));
            uint64_t u_cd = pk2(ex2f_fast(x2), ex2f_fast(x3));
            #pragma unroll
            for (int e = 0; e < 2; ++e) {
                uint64_t u = (e == 0) ? u_ab : u_cd;
                uint64_t u2 = mul2(u, u);
                uint64_t u4 = mul2(u2, u2);
                uint64_t u8 = mul2(u4, u4);
                uint64_t hi = fma2(u8, u8, u8);           // u16 + u8
                part2 = add2(part2, add2(add2(u, u2), add2(u4, hi)));
            }
        }
    }
    float plo, phi;
    unpk2(plo, phi, part2);
    float partial = plo + phi;
    float sgn = ((ib < 32) == (jb < 32)) ? 1.0f : -1.0f;
    partial *= (ib == jb) ? sgn : 2.0f * sgn;

    s_red[tid] = partial;
    __syncthreads();
    if (tid < 64) s_red[tid] += s_red[tid + 64];
    __syncthreads();
    if (tid < 32) {
        float v = s_red[tid] + s_red[tid + 32];
        #pragma unroll
        for (int o = 16; o; o >>= 1) v += __shfl_down_sync(0xffffffffu, v, o);
        if (tid == 0) atomicAdd(&g_acc, (double)v);
    }

    // last CTA writes the result
    if (tid == 0) {
        __threadfence();
        unsigned d = atomicAdd(&g_mctr, 1u);
        if (d == NBLK - 1) {
            out[0] = (float)(g_acc / ((double)NHALF * (double)NHALF));
            g_mctr = 0;      // reset for next graph replay
        }
    }
}

// ---------------------------------------------------------------------------
extern "C" void kernel_launch(void* const* d_in, const int* in_sizes, int n_in,
                              void* d_out, int out_size) {
    const float* s = (const float*)d_in[0];
    const float* t = (const float*)d_in[1];
    float* out = (float*)d_out;

    cudaFuncSetAttribute(k_mmd, cudaFuncAttributeMaxDynamicSharedMemorySize, SMEM_TOTAL);

    k_prep<<<PREPB, 256>>>(s, t);
    k_mmd<<<NBLK, 128, SMEM_TOTAL>>>(out);
}

// round 16
// speedup vs baseline: 1.1891x; 1.0304x over previous
#include <cuda_runtime.h>
#include <cuda_bf16.h>
#include <cstdint>

#define NS    8192
#define NHALF 4096
#define D     256
#define TS    128          // output tile (M=N)
#define KC    128          // int8 K elems per smem stage (128 B rows)
#define NSTAGE (D / KC)    // 2
#define NTILE  64          // NS / TS
#define NBLK   (NTILE * (NTILE + 1) / 2)   // 2080 upper-triangle tiles
#define PREPB  256         // k_prep blocks (32 rows each)

// ---- device-global scratch (no allocs allowed) ------------------------------
__device__ double g_acc;
__device__ float  g_colpart[PREPB * D];      // per-block column-sum partials
__device__ float  g_sqpart[PREPB];           // per-block sum-of-norms partials
__device__ float  g_sq[NS];                  // exact fp32 row norms
__device__ float  g_sc[NS];                  // per-row quant scale s_i = max/127
__device__ float  g_C;                       // log2(e) / (16*b)
__device__ unsigned g_pctr = 0;              // k_prep completion counter
__device__ unsigned g_mctr = 0;              // k_mmd completion counter
__device__ __align__(16) int8_t g_Y[(size_t)NS * D];   // 2 MB quantized rows

// ---- helpers ----------------------------------------------------------------
__device__ __forceinline__ float ex2f_fast(float x) {
    float y; asm("ex2.approx.f32 %0, %1;" : "=f"(y) : "f"(x)); return y;
}
__device__ __forceinline__ uint32_t smem_u32(const void* p) {
    uint32_t a;
    asm("{ .reg .u64 t; cvta.to.shared.u64 t, %1; cvt.u32.u64 %0, t; }" : "=r"(a) : "l"(p));
    return a;
}
__device__ __forceinline__ void cp16(uint32_t dst, const void* src) {
    asm volatile("cp.async.cg.shared.global [%0], [%1], 16;" :: "r"(dst), "l"(src));
}
#define CP_COMMIT() asm volatile("cp.async.commit_group;" ::: "memory")
#define CP_WAIT(n)  asm volatile("cp.async.wait_group %0;" :: "n"(n) : "memory")

__device__ __forceinline__ void ldm4(uint32_t* r, uint32_t a) {
    asm volatile("ldmatrix.sync.aligned.m8n8.x4.shared.b16 {%0,%1,%2,%3}, [%4];"
        : "=r"(r[0]), "=r"(r[1]), "=r"(r[2]), "=r"(r[3]) : "r"(a));
}
// s8 IMMA m16n8k32, s32 accumulate
__device__ __forceinline__ void imma16832(int* c, const uint32_t* a, const uint32_t* b) {
    asm volatile("mma.sync.aligned.m16n8k32.row.col.s32.s8.s8.s32 "
        "{%0,%1,%2,%3}, {%4,%5,%6,%7}, {%8,%9}, {%0,%1,%2,%3};"
        : "+r"(c[0]), "+r"(c[1]), "+r"(c[2]), "+r"(c[3])
        : "r"(a[0]), "r"(a[1]), "r"(a[2]), "r"(a[3]), "r"(b[0]), "r"(b[1]));
}

// ---- packed f32x2 (Blackwell FFMA2/FADD2 pipe) ------------------------------
__device__ __forceinline__ uint64_t pk2(float lo, float hi) {
    uint64_t r; asm("mov.b64 %0, {%1, %2};" : "=l"(r) : "f"(lo), "f"(hi)); return r;
}
__device__ __forceinline__ void unpk2(float& lo, float& hi, uint64_t v) {
    asm("mov.b64 {%0, %1}, %2;" : "=f"(lo), "=f"(hi) : "l"(v));
}
__device__ __forceinline__ uint64_t mul2(uint64_t a, uint64_t b) {
    uint64_t r; asm("mul.rn.f32x2 %0, %1, %2;" : "=l"(r) : "l"(a), "l"(b)); return r;
}
__device__ __forceinline__ uint64_t add2(uint64_t a, uint64_t b) {
    uint64_t r; asm("add.rn.f32x2 %0, %1, %2;" : "=l"(r) : "l"(a), "l"(b)); return r;
}
__device__ __forceinline__ uint64_t fma2(uint64_t a, uint64_t b, uint64_t c) {
    uint64_t r; asm("fma.rn.f32x2 %0, %1, %2, %3;" : "=l"(r) : "l"(a), "l"(b), "l"(c)); return r;
}

// SW128-style XOR swizzle for tiles with 128-byte rows (cp path only).
__device__ __forceinline__ uint32_t swz(uint32_t off) {
    return off ^ ((off >> 3) & 0x70);
}

__device__ __forceinline__ const float* row_ptr(const float* __restrict__ s,
                                                const float* __restrict__ t, int i) {
    return (i < NHALF) ? (s + (size_t)i * D) : (t + (size_t)(i - NHALF) * D);
}

// ---------------------------------------------------------------------------
// Fused prep: per-row L2 norm (exact fp32), per-row int8 quantization,
// per-block column-sum/norm-sum partials; last block computes bandwidth g_C.
// Triggers programmatic launch of k_mmd once per-block work is done.
__global__ __launch_bounds__(256) void k_prep(const float* __restrict__ s,
                                              const float* __restrict__ t) {
    __shared__ float colp[8][256];
    __shared__ float wsum[8];
    __shared__ unsigned s_done;
    int warp = threadIdx.x >> 5, lane = threadIdx.x & 31;

    float4 ca = make_float4(0.f, 0.f, 0.f, 0.f);
    float4 cb = make_float4(0.f, 0.f, 0.f, 0.f);
    float normsum = 0.0f;

    #pragma unroll
    for (int r = 0; r < 4; ++r) {
        int row = blockIdx.x * 32 + warp * 4 + r;
        const float4* p = (const float4*)row_ptr(s, t, row);
        float4 a = p[lane];          // cols 4*lane .. 4*lane+3
        float4 b = p[lane + 32];     // cols 128+4*lane ..

        float v = a.x * a.x + a.y * a.y + a.z * a.z + a.w * a.w
                + b.x * b.x + b.y * b.y + b.z * b.z + b.w * b.w;
        float m = fmaxf(fmaxf(fmaxf(fabsf(a.x), fabsf(a.y)), fmaxf(fabsf(a.z), fabsf(a.w))),
                        fmaxf(fmaxf(fabsf(b.x), fabsf(b.y)), fmaxf(fabsf(b.z), fabsf(b.w))));
        #pragma unroll
        for (int o = 16; o; o >>= 1) {
            v += __shfl_xor_sync(0xffffffffu, v, o);
            m  = fmaxf(m, __shfl_xor_sync(0xffffffffu, m, o));
        }
        if (lane == 0) {
            g_sq[row] = v;
            g_sc[row] = m * (1.0f / 127.0f);
            normsum += v;
        }

        // quantize: q = round(x * 127/m), pack 4 x s8 per u32
        float inv = (m > 0.0f) ? (127.0f / m) : 0.0f;
        int qa0 = __float2int_rn(a.x * inv), qa1 = __float2int_rn(a.y * inv);
        int qa2 = __float2int_rn(a.z * inv), qa3 = __float2int_rn(a.w * inv);
        int qb0 = __float2int_rn(b.x * inv), qb1 = __float2int_rn(b.y * inv);
        int qb2 = __float2int_rn(b.z * inv), qb3 = __float2int_rn(b.w * inv);
        uint32_t ua = (uint32_t)(qa0 & 0xFF) | ((uint32_t)(qa1 & 0xFF) << 8)
                    | ((uint32_t)(qa2 & 0xFF) << 16) | ((uint32_t)qa3 << 24);
        uint32_t ub = (uint32_t)(qb0 & 0xFF) | ((uint32_t)(qb1 & 0xFF) << 8)
                    | ((uint32_t)(qb2 & 0xFF) << 16) | ((uint32_t)qb3 << 24);
        uint32_t* yrow = (uint32_t*)(g_Y + (size_t)row * D);
        yrow[lane]      = ua;
        yrow[lane + 32] = ub;

        ca.x += a.x; ca.y += a.y; ca.z += a.z; ca.w += a.w;
        cb.x += b.x; cb.y += b.y; cb.z += b.z; cb.w += b.w;
    }

    ((float4*)colp[warp])[lane]      = ca;
    ((float4*)colp[warp])[lane + 32] = cb;
    if (lane == 0) wsum[warp] = normsum;
    __syncthreads();

    int tid = threadIdx.x;           // 0..255 = column index
    float cs = 0.0f;
    #pragma unroll
    for (int w = 0; w < 8; ++w) cs += colp[w][tid];
    g_colpart[blockIdx.x * D + tid] = cs;
    if (tid == 0) {
        float ss = 0.0f;
        #pragma unroll
        for (int w = 0; w < 8; ++w) ss += wsum[w];
        g_sqpart[blockIdx.x] = ss;
        g_acc = 0.0;
    }

    // allow the dependent k_mmd grid to begin launching (its CTAs still wait
    // on cudaGridDependencySynchronize before consuming our outputs)
    cudaTriggerProgrammaticLaunchCompletion();

    // last-block bandwidth computation
    __threadfence();
    if (tid == 0) s_done = atomicAdd(&g_pctr, 1u);
    __syncthreads();
    if (s_done == PREPB - 1) {
        __shared__ float red[256];
        float c2 = 0.0f;
        #pragma unroll 8
        for (int b = 0; b < PREPB; ++b) c2 += g_colpart[b * D + tid];
        red[tid] = c2 * c2;
        __syncthreads();
        for (int o = 128; o; o >>= 1) { if (tid < o) red[tid] += red[tid + o]; __syncthreads(); }
        float csq = red[0];
        __syncthreads();
        red[tid] = g_sqpart[tid];        // PREPB == 256
        __syncthreads();
        for (int o = 128; o; o >>= 1) { if (tid < o) red[tid] += red[tid + o]; __syncthreads(); }
        if (tid == 0) {
            double suml2 = 2.0 * (double)NS * (double)red[0] - 2.0 * (double)csq;
            double bw = suml2 / ((double)NS * (double)NS - (double)NS);
            double b = bw / 4.0;     // KERNEL_MUL^(KERNEL_NUM//2) = 2^2
            g_C = (float)(1.4426950408889634 / (16.0 * b));
            g_pctr = 0;              // reset for next graph replay
        }
    }
}

// ---------------------------------------------------------------------------
// INT8 warp-IMMA fused Gram + Gaussian epilogue. 2080 CTAs, 4 warps each,
// 64x64 warp tiles over 128x128. K=256 int8 in 2 stages of 128 (128B rows),
// cp.async double-buffered, register double-buffered fragments, s8 IMMA k32.
// 3 CTAs/SM; fully-packed f32x2 epilogue. Launched via PDL: prologue overlaps
// k_prep; cudaGridDependencySynchronize() gates the first g_Y/g_sq/g_C use.
#define STAGE_BYTES 32768                    // A(16KB) + B(16KB)
#define SMEM_TOTAL  (2 * STAGE_BYTES)        // 64KB dyn; 3 CTAs/SM ~ 200KB

__device__ __forceinline__ void load_frags(uint32_t Ab, uint32_t Bb, uint32_t koff,
                                           const uint32_t* ra, const uint32_t* rb,
                                           uint32_t afr[4][4], uint32_t bfr[8][2]) {
    #pragma unroll
    for (int i = 0; i < 4; ++i)
        ldm4(afr[i], Ab + ra[i] + koff);
    #pragma unroll
    for (int j2 = 0; j2 < 4; ++j2) {
        uint32_t q[4];
        ldm4(q, Bb + rb[j2] + koff);
        bfr[j2 * 2 + 0][0] = q[0]; bfr[j2 * 2 + 0][1] = q[2];
        bfr[j2 * 2 + 1][0] = q[1]; bfr[j2 * 2 + 1][1] = q[3];
    }
}

__global__ __launch_bounds__(128, 3) void k_mmd(float* __restrict__ out) {
    // ---- prologue (overlaps k_prep under PDL) ----
    // linear bid -> (ib, jb), jb >= ib.
    int bid = blockIdx.x;
    int ib = (int)(64.5f - sqrtf(64.5f * 64.5f - 2.0f * (float)bid));
    #pragma unroll 1
    while ((64 * (ib + 1) - ((ib + 1) * ib) / 2) <= bid) ++ib;
    #pragma unroll 1
    while ((64 * ib - (ib * (ib - 1)) / 2) > bid) --ib;
    int jb = ib + (bid - (64 * ib - (ib * (ib - 1)) / 2));

    extern __shared__ char sm[];
    __shared__ __align__(16) float s_nCi[128], s_nCj[128], s_sci[128], s_scj[128];
    __shared__ float s_red[128];
    uint32_t sbase = smem_u32(sm);

    int tid  = threadIdx.x;
    int warp = tid >> 5, lane = tid & 31;
    int wm = warp >> 1, wn = warp & 1;        // warp tile: rows wm*64, cols wn*64
    int rI = ib * TS, rJ = jb * TS;

    // hoisted LDSM addressing: swz(row*128+kb) == row*128 + (kb ^ ((lane&7)<<4))
    int lane15 = lane & 15;
    uint32_t xr  = (uint32_t)((lane & 7) << 4);
    uint32_t kb0 = (uint32_t)((lane >> 4) * 16);
    uint32_t ra[4], rb[4];
    #pragma unroll
    for (int i = 0; i < 4; ++i) {
        ra[i] = (uint32_t)((wm * 64 + i * 16 + lane15) * 128);
        rb[i] = (uint32_t)((wn * 64 + i * 16 + lane15) * 128);
    }

    // ---- wait for k_prep's outputs (g_Y, g_sq, g_sc, g_C) ----
    cudaGridDependencySynchronize();

    float C = g_C;
    s_nCi[tid] = -C * g_sq[rI + tid];
    s_nCj[tid] = -C * g_sq[rJ + tid];
    s_sci[tid] = 2.0f * C * g_sc[rI + tid];   // pre-scaled row quant scale
    s_scj[tid] = g_sc[rJ + tid];

    const int8_t* YA = g_Y + (size_t)rI * D;
    const int8_t* YB = g_Y + (size_t)rJ * D;

    auto issue_stage = [&](int st, int buf) {
        int k0 = st * KC;                      // byte offset within 256B row
        uint32_t base = sbase + buf * STAGE_BYTES;
        #pragma unroll
        for (int t = 0; t < 8; ++t) {
            int chunk = tid + t * 128;           // 0..1023
            int r = chunk >> 3, c16 = chunk & 7;
            uint32_t d = swz((uint32_t)(r * 128 + c16 * 16));
            cp16(base + d,         YA + (size_t)r * D + k0 + c16 * 16);
            cp16(base + 16384 + d, YB + (size_t)r * D + k0 + c16 * 16);
        }
        CP_COMMIT();
    };

    int acc[4][8][4] = {};
    uint32_t afr[2][4][4], bfr[2][8][2];

    issue_stage(0, 0);
    issue_stage(1, 1);

    #pragma unroll
    for (int st = 0; st < NSTAGE; ++st) {
        if (st == 0) CP_WAIT(1);
        else         CP_WAIT(0);
        __syncthreads();

        uint32_t Ab = sbase + st * STAGE_BYTES;
        uint32_t Bb = Ab + 16384;

        load_frags(Ab, Bb, kb0 ^ xr, ra, rb, afr[0], bfr[0]);
        #pragma unroll
        for (int kk = 0; kk < 4; ++kk) {       // 4 k-steps of k=32 per stage
            int cur = kk & 1;
            if (kk < 3) {
                uint32_t koff = ((uint32_t)((kk + 1) << 5) | kb0) ^ xr;
                load_frags(Ab, Bb, koff, ra, rb, afr[cur ^ 1], bfr[cur ^ 1]);
            }
            #pragma unroll
            for (int i = 0; i < 4; ++i)
                #pragma unroll
                for (int j = 0; j < 8; ++j)
                    imma16832(acc[i][j], afr[cur][i], bfr[cur][j]);
        }
        __syncthreads();
    }

    // ---- fused epilogue (fully packed f32x2):
    //   arg2 = fma2(mul2(si2, sj2), accf2, add2(ni2, nj2));  u = exp2(arg)
    //   powersum = u + u^2 + u^4 + u^8 + u^16  (packed pairs)
    uint64_t part2 = pk2(0.0f, 0.0f);
    #pragma unroll
    for (int i = 0; i < 4; ++i) {
        int r_lo = wm * 64 + i * 16 + (lane >> 2);
        uint64_t ni2_lo = pk2(s_nCi[r_lo],     s_nCi[r_lo]);
        uint64_t ni2_hi = pk2(s_nCi[r_lo + 8], s_nCi[r_lo + 8]);
        uint64_t si2_lo = pk2(s_sci[r_lo],     s_sci[r_lo]);
        uint64_t si2_hi = pk2(s_sci[r_lo + 8], s_sci[r_lo + 8]);
        #pragma unroll
        for (int j = 0; j < 8; ++j) {
            int c_lo = wn * 64 + j * 8 + (lane & 3) * 2;
            uint64_t nj2 = *reinterpret_cast<const uint64_t*>(&s_nCj[c_lo]);
            uint64_t sj2 = *reinterpret_cast<const uint64_t*>(&s_scj[c_lo]);
            uint64_t arg_lo = fma2(mul2(si2_lo, sj2),
                                   pk2((float)acc[i][j][0], (float)acc[i][j][1]),
                                   add2(ni2_lo, nj2));
            uint64_t arg_hi = fma2(mul2(si2_hi, sj2),
                                   pk2((float)acc[i][j][2], (float)acc[i][j][3]),
                                   add2(ni2_hi, nj2));
            float x0, x1, x2, x3;
            unpk2(x0, x1, arg_lo);
            unpk2(x2, x3, arg_hi);
            uint64_t u_ab = pk2(ex2f_fast(x0), ex2f_fast(x1));
            uint64_t u_cd = pk2(ex2f_fast(x2), ex2f_fast(x3));
            #pragma unroll
            for (int e = 0; e < 2; ++e) {
                uint64_t u = (e == 0) ? u_ab : u_cd;
                uint64_t u2 = mul2(u, u);
                uint64_t u4 = mul2(u2, u2);
                uint64_t u8 = mul2(u4, u4);
                uint64_t hi = fma2(u8, u8, u8);           // u16 + u8
                part2 = add2(part2, add2(add2(u, u2), add2(u4, hi)));
            }
        }
    }
    float plo, phi;
    unpk2(plo, phi, part2);
    float partial = plo + phi;
    float sgn = ((ib < 32) == (jb < 32)) ? 1.0f : -1.0f;
    partial *= (ib == jb) ? sgn : 2.0f * sgn;

    s_red[tid] = partial;
    __syncthreads();
    if (tid < 64) s_red[tid] += s_red[tid + 64];
    __syncthreads();
    if (tid < 32) {
        float v = s_red[tid] + s_red[tid + 32];
        #pragma unroll
        for (int o = 16; o; o >>= 1) v += __shfl_down_sync(0xffffffffu, v, o);
        if (tid == 0) atomicAdd(&g_acc, (double)v);
    }

    // last CTA writes the result
    if (tid == 0) {
        __threadfence();
        unsigned d = atomicAdd(&g_mctr, 1u);
        if (d == NBLK - 1) {
            out[0] = (float)(g_acc / ((double)NHALF * (double)NHALF));
            g_mctr = 0;      // reset for next graph replay
        }
    }
}

// ---------------------------------------------------------------------------
extern "C" void kernel_launch(void* const* d_in, const int* in_sizes, int n_in,
                              void* d_out, int out_size) {
    const float* s = (const float*)d_in[0];
    const float* t = (const float*)d_in[1];
    float* out = (float*)d_out;

    cudaFuncSetAttribute(k_mmd, cudaFuncAttributeMaxDynamicSharedMemorySize, SMEM_TOTAL);

    k_prep<<<PREPB, 256>>>(s, t);

    // PDL launch: k_mmd may begin launching once k_prep triggers; its CTAs
    // gate on cudaGridDependencySynchronize() before consuming prep outputs.
    cudaLaunchConfig_t cfg = {};
    cfg.gridDim = dim3(NBLK, 1, 1);
    cfg.blockDim = dim3(128, 1, 1);
    cfg.dynamicSmemBytes = SMEM_TOTAL;
    cfg.stream = 0;
    cudaLaunchAttribute attr[1];
    attr[0].id = cudaLaunchAttributeProgrammaticStreamSerialization;
    attr[0].val.programmaticStreamSerializationAllowed = 1;
    cfg.attrs = attr;
    cfg.numAttrs = 1;
    cudaLaunchKernelEx(&cfg, k_mmd, out);
}

// round 17
// speedup vs baseline: 1.3356x; 1.1233x over previous
#include <cuda_runtime.h>
#include <cuda_bf16.h>
#include <cstdint>

#define NS    8192
#define NHALF 4096
#define D     256
#define TS    128          // output tile (M=N)
#define KC    128          // int8 K elems per smem stage (128 B rows)
#define NSTAGE (D / KC)    // 2
#define NTILE  64          // NS / TS
#define NBLK   (NTILE * (NTILE + 1) / 2)   // 2080 upper-triangle tiles
#define PREPB  512         // k_prep blocks (16 rows each)

// ---- device-global scratch (no allocs allowed) ------------------------------
__device__ double g_acc;
__device__ float  g_colsum[D];               // atomic-accumulated column sums
__device__ float  g_sumsq;                   // atomic-accumulated sum of norms
__device__ float  g_sq[NS];                  // exact fp32 row norms
__device__ float  g_sc[NS];                  // per-row quant scale s_i = max/127
__device__ float  g_C;                       // log2(e) / (16*b)
__device__ unsigned g_pctr = 0;              // k_prep completion counter
__device__ unsigned g_mctr = 0;              // k_mmd completion counter
__device__ __align__(16) int8_t g_Y[(size_t)NS * D];   // 2 MB quantized rows

// ---- helpers ----------------------------------------------------------------
__device__ __forceinline__ float ex2f_fast(float x) {
    float y; asm("ex2.approx.f32 %0, %1;" : "=f"(y) : "f"(x)); return y;
}
__device__ __forceinline__ uint32_t smem_u32(const void* p) {
    uint32_t a;
    asm("{ .reg .u64 t; cvta.to.shared.u64 t, %1; cvt.u32.u64 %0, t; }" : "=r"(a) : "l"(p));
    return a;
}
__device__ __forceinline__ void cp16(uint32_t dst, const void* src) {
    asm volatile("cp.async.cg.shared.global [%0], [%1], 16;" :: "r"(dst), "l"(src));
}
#define CP_COMMIT() asm volatile("cp.async.commit_group;" ::: "memory")
#define CP_WAIT(n)  asm volatile("cp.async.wait_group %0;" :: "n"(n) : "memory")

__device__ __forceinline__ void ldm4(uint32_t* r, uint32_t a) {
    asm volatile("ldmatrix.sync.aligned.m8n8.x4.shared.b16 {%0,%1,%2,%3}, [%4];"
        : "=r"(r[0]), "=r"(r[1]), "=r"(r[2]), "=r"(r[3]) : "r"(a));
}
// s8 IMMA m16n8k32, s32 accumulate
__device__ __forceinline__ void imma16832(int* c, const uint32_t* a, const uint32_t* b) {
    asm volatile("mma.sync.aligned.m16n8k32.row.col.s32.s8.s8.s32 "
        "{%0,%1,%2,%3}, {%4,%5,%6,%7}, {%8,%9}, {%0,%1,%2,%3};"
        : "+r"(c[0]), "+r"(c[1]), "+r"(c[2]), "+r"(c[3])
        : "r"(a[0]), "r"(a[1]), "r"(a[2]), "r"(a[3]), "r"(b[0]), "r"(b[1]));
}

// ---- packed f32x2 (Blackwell FFMA2/FADD2 pipe) ------------------------------
__device__ __forceinline__ uint64_t pk2(float lo, float hi) {
    uint64_t r; asm("mov.b64 %0, {%1, %2};" : "=l"(r) : "f"(lo), "f"(hi)); return r;
}
__device__ __forceinline__ void unpk2(float& lo, float& hi, uint64_t v) {
    asm("mov.b64 {%0, %1}, %2;" : "=f"(lo), "=f"(hi) : "l"(v));
}
__device__ __forceinline__ uint64_t mul2(uint64_t a, uint64_t b) {
    uint64_t r; asm("mul.rn.f32x2 %0, %1, %2;" : "=l"(r) : "l"(a), "l"(b)); return r;
}
__device__ __forceinline__ uint64_t add2(uint64_t a, uint64_t b) {
    uint64_t r; asm("add.rn.f32x2 %0, %1, %2;" : "=l"(r) : "l"(a), "l"(b)); return r;
}
__device__ __forceinline__ uint64_t fma2(uint64_t a, uint64_t b, uint64_t c) {
    uint64_t r; asm("fma.rn.f32x2 %0, %1, %2, %3;" : "=l"(r) : "l"(a), "l"(b), "l"(c)); return r;
}

// SW128-style XOR swizzle for tiles with 128-byte rows (cp path only).
__device__ __forceinline__ uint32_t swz(uint32_t off) {
    return off ^ ((off >> 3) & 0x70);
}

__device__ __forceinline__ const float* row_ptr(const float* __restrict__ s,
                                                const float* __restrict__ t, int i) {
    return (i < NHALF) ? (s + (size_t)i * D) : (t + (size_t)(i - NHALF) * D);
}

// ---------------------------------------------------------------------------
// Fused prep: per-row L2 norm (exact fp32), per-row int8 quantization,
// atomic column-sum/norm-sum accumulation; last block computes bandwidth g_C.
// Triggers programmatic launch of k_mmd once per-block work is done.
// (g_colsum / g_sumsq start at 0: static init first run, reset by k_mmd's
//  last CTA on every run for graph replay.)
__global__ __launch_bounds__(256) void k_prep(const float* __restrict__ s,
                                              const float* __restrict__ t) {
    __shared__ float colp[8][256];
    __shared__ float wsum[8];
    __shared__ unsigned s_done;
    int warp = threadIdx.x >> 5, lane = threadIdx.x & 31;

    float4 ca = make_float4(0.f, 0.f, 0.f, 0.f);
    float4 cb = make_float4(0.f, 0.f, 0.f, 0.f);
    float normsum = 0.0f;

    #pragma unroll
    for (int r = 0; r < 2; ++r) {
        int row = blockIdx.x * 16 + warp * 2 + r;
        const float4* p = (const float4*)row_ptr(s, t, row);
        float4 a = p[lane];          // cols 4*lane .. 4*lane+3
        float4 b = p[lane + 32];     // cols 128+4*lane ..

        float v = a.x * a.x + a.y * a.y + a.z * a.z + a.w * a.w
                + b.x * b.x + b.y * b.y + b.z * b.z + b.w * b.w;
        float m = fmaxf(fmaxf(fmaxf(fabsf(a.x), fabsf(a.y)), fmaxf(fabsf(a.z), fabsf(a.w))),
                        fmaxf(fmaxf(fabsf(b.x), fabsf(b.y)), fmaxf(fabsf(b.z), fabsf(b.w))));
        #pragma unroll
        for (int o = 16; o; o >>= 1) {
            v += __shfl_xor_sync(0xffffffffu, v, o);
            m  = fmaxf(m, __shfl_xor_sync(0xffffffffu, m, o));
        }
        if (lane == 0) {
            g_sq[row] = v;
            g_sc[row] = m * (1.0f / 127.0f);
            normsum += v;
        }

        // quantize: q = round(x * 127/m), pack 4 x s8 per u32
        float inv = (m > 0.0f) ? (127.0f / m) : 0.0f;
        int qa0 = __float2int_rn(a.x * inv), qa1 = __float2int_rn(a.y * inv);
        int qa2 = __float2int_rn(a.z * inv), qa3 = __float2int_rn(a.w * inv);
        int qb0 = __float2int_rn(b.x * inv), qb1 = __float2int_rn(b.y * inv);
        int qb2 = __float2int_rn(b.z * inv), qb3 = __float2int_rn(b.w * inv);
        uint32_t ua = (uint32_t)(qa0 & 0xFF) | ((uint32_t)(qa1 & 0xFF) << 8)
                    | ((uint32_t)(qa2 & 0xFF) << 16) | ((uint32_t)qa3 << 24);
        uint32_t ub = (uint32_t)(qb0 & 0xFF) | ((uint32_t)(qb1 & 0xFF) << 8)
                    | ((uint32_t)(qb2 & 0xFF) << 16) | ((uint32_t)qb3 << 24);
        uint32_t* yrow = (uint32_t*)(g_Y + (size_t)row * D);
        yrow[lane]      = ua;
        yrow[lane + 32] = ub;

        ca.x += a.x; ca.y += a.y; ca.z += a.z; ca.w += a.w;
        cb.x += b.x; cb.y += b.y; cb.z += b.z; cb.w += b.w;
    }

    ((float4*)colp[warp])[lane]      = ca;
    ((float4*)colp[warp])[lane + 32] = cb;
    if (lane == 0) wsum[warp] = normsum;
    __syncthreads();

    int tid = threadIdx.x;           // 0..255 = column index
    float cs = 0.0f;
    #pragma unroll
    for (int w = 0; w < 8; ++w) cs += colp[w][tid];
    atomicAdd(&g_colsum[tid], cs);
    if (tid == 0) {
        atomicAdd(&g_sumsq, wsum[0] + wsum[1] + wsum[2] + wsum[3]
                          + wsum[4] + wsum[5] + wsum[6] + wsum[7]);
        g_acc = 0.0;
    }

    // allow the dependent k_mmd grid to begin launching (its CTAs still wait
    // on cudaGridDependencySynchronize before consuming our outputs)
    cudaTriggerProgrammaticLaunchCompletion();

    // last-block bandwidth computation (g_colsum/g_sumsq complete by fence+ctr)
    __threadfence();
    if (tid == 0) s_done = atomicAdd(&g_pctr, 1u);
    __syncthreads();
    if (s_done == PREPB - 1) {
        __shared__ float red[256];
        float c = g_colsum[tid];
        red[tid] = c * c;
        __syncthreads();
        for (int o = 128; o; o >>= 1) { if (tid < o) red[tid] += red[tid + o]; __syncthreads(); }
        if (tid == 0) {
            double suml2 = 2.0 * (double)NS * (double)g_sumsq - 2.0 * (double)red[0];
            double bw = suml2 / ((double)NS * (double)NS - (double)NS);
            double b = bw / 4.0;     // KERNEL_MUL^(KERNEL_NUM//2) = 2^2
            g_C = (float)(1.4426950408889634 / (16.0 * b));
            g_pctr = 0;              // reset for next graph replay
        }
    }
}

// ---------------------------------------------------------------------------
// INT8 warp-IMMA fused Gram + Gaussian epilogue. 2080 CTAs, 4 warps each,
// 64x64 warp tiles over 128x128. K=256 int8 in 2 stages of 128 (128B rows),
// cp.async double-buffered, register double-buffered fragments, s8 IMMA k32.
// 3 CTAs/SM; fully-packed f32x2 epilogue with dual accumulators. PDL-launched.
#define STAGE_BYTES 32768                    // A(16KB) + B(16KB)
#define SMEM_TOTAL  (2 * STAGE_BYTES)        // 64KB dyn; 3 CTAs/SM ~ 200KB

__device__ __forceinline__ void load_frags(uint32_t Ab, uint32_t Bb, uint32_t koff,
                                           const uint32_t* ra, const uint32_t* rb,
                                           uint32_t afr[4][4], uint32_t bfr[8][2]) {
    #pragma unroll
    for (int i = 0; i < 4; ++i)
        ldm4(afr[i], Ab + ra[i] + koff);
    #pragma unroll
    for (int j2 = 0; j2 < 4; ++j2) {
        uint32_t q[4];
        ldm4(q, Bb + rb[j2] + koff);
        bfr[j2 * 2 + 0][0] = q[0]; bfr[j2 * 2 + 0][1] = q[2];
        bfr[j2 * 2 + 1][0] = q[1]; bfr[j2 * 2 + 1][1] = q[3];
    }
}

__global__ __launch_bounds__(128, 3) void k_mmd(float* __restrict__ out) {
    // ---- prologue (overlaps k_prep under PDL) ----
    int bid = blockIdx.x;
    int ib = (int)(64.5f - sqrtf(64.5f * 64.5f - 2.0f * (float)bid));
    #pragma unroll 1
    while ((64 * (ib + 1) - ((ib + 1) * ib) / 2) <= bid) ++ib;
    #pragma unroll 1
    while ((64 * ib - (ib * (ib - 1)) / 2) > bid) --ib;
    int jb = ib + (bid - (64 * ib - (ib * (ib - 1)) / 2));

    extern __shared__ char sm[];
    __shared__ __align__(16) float s_nCi[128], s_nCj[128], s_sci[128], s_scj[128];
    __shared__ float s_red[128];
    uint32_t sbase = smem_u32(sm);

    int tid  = threadIdx.x;
    int warp = tid >> 5, lane = tid & 31;
    int wm = warp >> 1, wn = warp & 1;        // warp tile: rows wm*64, cols wn*64
    int rI = ib * TS, rJ = jb * TS;

    // hoisted LDSM addressing: swz(row*128+kb) == row*128 + (kb ^ ((lane&7)<<4))
    int lane15 = lane & 15;
    uint32_t xr  = (uint32_t)((lane & 7) << 4);
    uint32_t kb0 = (uint32_t)((lane >> 4) * 16);
    uint32_t ra[4], rb[4];
    #pragma unroll
    for (int i = 0; i < 4; ++i) {
        ra[i] = (uint32_t)((wm * 64 + i * 16 + lane15) * 128);
        rb[i] = (uint32_t)((wn * 64 + i * 16 + lane15) * 128);
    }

    // ---- wait for k_prep's outputs (g_Y, g_sq, g_sc, g_C) ----
    cudaGridDependencySynchronize();

    float C = g_C;
    s_nCi[tid] = -C * g_sq[rI + tid];
    s_nCj[tid] = -C * g_sq[rJ + tid];
    s_sci[tid] = 2.0f * C * g_sc[rI + tid];   // pre-scaled row quant scale
    s_scj[tid] = g_sc[rJ + tid];

    const int8_t* YA = g_Y + (size_t)rI * D;
    const int8_t* YB = g_Y + (size_t)rJ * D;

    auto issue_stage = [&](int st, int buf) {
        int k0 = st * KC;                      // byte offset within 256B row
        uint32_t base = sbase + buf * STAGE_BYTES;
        #pragma unroll
        for (int t = 0; t < 8; ++t) {
            int chunk = tid + t * 128;           // 0..1023
            int r = chunk >> 3, c16 = chunk & 7;
            uint32_t d = swz((uint32_t)(r * 128 + c16 * 16));
            cp16(base + d,         YA + (size_t)r * D + k0 + c16 * 16);
            cp16(base + 16384 + d, YB + (size_t)r * D + k0 + c16 * 16);
        }
        CP_COMMIT();
    };

    int acc[4][8][4] = {};
    uint32_t afr[2][4][4], bfr[2][8][2];

    issue_stage(0, 0);
    issue_stage(1, 1);

    #pragma unroll
    for (int st = 0; st < NSTAGE; ++st) {
        if (st == 0) CP_WAIT(1);
        else         CP_WAIT(0);
        __syncthreads();

        uint32_t Ab = sbase + st * STAGE_BYTES;
        uint32_t Bb = Ab + 16384;

        load_frags(Ab, Bb, kb0 ^ xr, ra, rb, afr[0], bfr[0]);
        #pragma unroll
        for (int kk = 0; kk < 4; ++kk) {       // 4 k-steps of k=32 per stage
            int cur = kk & 1;
            if (kk < 3) {
                uint32_t koff = ((uint32_t)((kk + 1) << 5) | kb0) ^ xr;
                load_frags(Ab, Bb, koff, ra, rb, afr[cur ^ 1], bfr[cur ^ 1]);
            }
            #pragma unroll
            for (int i = 0; i < 4; ++i)
                #pragma unroll
                for (int j = 0; j < 8; ++j)
                    imma16832(acc[i][j], afr[cur][i], bfr[cur][j]);
        }
        __syncthreads();
    }

    // ---- fused epilogue (fully packed f32x2, dual accumulators):
    //   arg2 = fma2(mul2(si2, sj2), accf2, add2(ni2, nj2));  u = exp2(arg)
    //   powersum = u + u^2 + u^4 + u^8 + u^16  (packed pairs)
    uint64_t partA = pk2(0.0f, 0.0f);
    uint64_t partB = pk2(0.0f, 0.0f);
    #pragma unroll
    for (int i = 0; i < 4; ++i) {
        int r_lo = wm * 64 + i * 16 + (lane >> 2);
        uint64_t ni2_lo = pk2(s_nCi[r_lo],     s_nCi[r_lo]);
        uint64_t ni2_hi = pk2(s_nCi[r_lo + 8], s_nCi[r_lo + 8]);
        uint64_t si2_lo = pk2(s_sci[r_lo],     s_sci[r_lo]);
        uint64_t si2_hi = pk2(s_sci[r_lo + 8], s_sci[r_lo + 8]);
        #pragma unroll
        for (int j = 0; j < 8; ++j) {
            int c_lo = wn * 64 + j * 8 + (lane & 3) * 2;
            uint64_t nj2 = *reinterpret_cast<const uint64_t*>(&s_nCj[c_lo]);
            uint64_t sj2 = *reinterpret_cast<const uint64_t*>(&s_scj[c_lo]);
            uint64_t arg_lo = fma2(mul2(si2_lo, sj2),
                                   pk2((float)acc[i][j][0], (float)acc[i][j][1]),
                                   add2(ni2_lo, nj2));
            uint64_t arg_hi = fma2(mul2(si2_hi, sj2),
                                   pk2((float)acc[i][j][2], (float)acc[i][j][3]),
                                   add2(ni2_hi, nj2));
            float x0, x1, x2, x3;
            unpk2(x0, x1, arg_lo);
            unpk2(x2, x3, arg_hi);
            uint64_t u_ab = pk2(ex2f_fast(x0), ex2f_fast(x1));
            uint64_t u_cd = pk2(ex2f_fast(x2), ex2f_fast(x3));
            {
                uint64_t u2 = mul2(u_ab, u_ab);
                uint64_t u4 = mul2(u2, u2);
                uint64_t u8 = mul2(u4, u4);
                uint64_t hi = fma2(u8, u8, u8);           // u16 + u8
                partA = add2(partA, add2(add2(u_ab, u2), add2(u4, hi)));
            }
            {
                uint64_t u2 = mul2(u_cd, u_cd);
                uint64_t u4 = mul2(u2, u2);
                uint64_t u8 = mul2(u4, u4);
                uint64_t hi = fma2(u8, u8, u8);           // u16 + u8
                partB = add2(partB, add2(add2(u_cd, u2), add2(u4, hi)));
            }
        }
    }
    uint64_t part2 = add2(partA, partB);
    float plo, phi;
    unpk2(plo, phi, part2);
    float partial = plo + phi;
    float sgn = ((ib < 32) == (jb < 32)) ? 1.0f : -1.0f;
    partial *= (ib == jb) ? sgn : 2.0f * sgn;

    s_red[tid] = partial;
    __syncthreads();
    if (tid < 64) s_red[tid] += s_red[tid + 64];
    __syncthreads();
    if (tid < 32) {
        float v = s_red[tid] + s_red[tid + 32];
        #pragma unroll
        for (int o = 16; o; o >>= 1) v += __shfl_down_sync(0xffffffffu, v, o);
        if (tid == 0) atomicAdd(&g_acc, (double)v);
    }

    // last CTA writes the result and resets accumulators for graph replay
    if (tid == 0) {
        __threadfence();
        unsigned d = atomicAdd(&g_mctr, 1u);
        if (d == NBLK - 1) {
            out[0] = (float)(g_acc / ((double)NHALF * (double)NHALF));
            g_mctr  = 0;
            g_sumsq = 0.0f;
            #pragma unroll 8
            for (int c = 0; c < D; ++c) g_colsum[c] = 0.0f;
        }
    }
}

// ---------------------------------------------------------------------------
extern "C" void kernel_launch(void* const* d_in, const int* in_sizes, int n_in,
                              void* d_out, int out_size) {
    const float* s = (const float*)d_in[0];
    const float* t = (const float*)d_in[1];
    float* out = (float*)d_out;

    cudaFuncSetAttribute(k_mmd, cudaFuncAttributeMaxDynamicSharedMemorySize, SMEM_TOTAL);

    k_prep<<<PREPB, 256>>>(s, t);

    // PDL launch: k_mmd may begin launching once k_prep triggers; its CTAs
    // gate on cudaGridDependencySynchronize() before consuming prep outputs.
    cudaLaunchConfig_t cfg = {};
    cfg.gridDim = dim3(NBLK, 1, 1);
    cfg.blockDim = dim3(128, 1, 1);
    cfg.dynamicSmemBytes = SMEM_TOTAL;
    cfg.stream = 0;
    cudaLaunchAttribute attr[1];
    attr[0].id = cudaLaunchAttributeProgrammaticStreamSerialization;
    attr[0].val.programmaticStreamSerializationAllowed = 1;
    cfg.attrs = attr;
    cfg.numAttrs = 1;
    cudaLaunchKernelEx(&cfg, k_mmd, out);
}